// round 10
// baseline (speedup 1.0000x reference)
#include <cuda_runtime.h>
#include <math.h>

// Problem constants (shapes fixed by the dataset)
#define MAX_N 50000
#define MAX_E 800000
#define FIN   256
#define HC    256     // H1*C1
#define H1N   4
#define C1N   64
#define F2    16

// ---------------- scratch (static device globals; no allocation) -------------
__device__ float g_h1 [MAX_N * HC];   // x@W1
__device__ float g_h1o[MAX_N * HC];   // layer1 output (bias+relu)
__device__ float g_h2 [MAX_N * F2];   // h1o@W2
__device__ float g_as1[MAX_N * H1N];
__device__ float g_ad1[MAX_N * H1N];
__device__ float g_as2[MAX_N];
__device__ float g_ad2[MAX_N];
__device__ int   g_deg [MAX_N];
__device__ int   g_cur [MAX_N];
__device__ int   g_offs[MAX_N + 1];
__device__ int   g_csr [MAX_E];       // src node ids grouped by dst

#define NEGBIG (-3.0e38f)

// ---------------- CSR build --------------------------------------------------
__global__ void init_kernel(int N) {
    int i = blockIdx.x * blockDim.x + threadIdx.x;
    if (i < N) { g_deg[i] = 0; g_cur[i] = 0; }
}

// edge_index is INT32 (JAX x64 disabled: randint(dtype=int64) silently yields int32)
__global__ void deg_kernel(const int* __restrict__ ei, int E) {
    int e = blockIdx.x * blockDim.x + threadIdx.x;
    if (e < E) {
        int d = ei[E + e];
        if (d >= 0 && d < MAX_N) atomicAdd(&g_deg[d], 1);
    }
}

// single-block exclusive scan of g_deg -> g_offs (N up to 50000)
__global__ void scan_kernel(int N) {
    __shared__ int wsum[32];
    __shared__ int carry_sh;
    int t = threadIdx.x;
    if (t == 0) carry_sh = 0;
    __syncthreads();
    for (int base = 0; base < N; base += 1024) {
        int i = base + t;
        int v = (i < N) ? g_deg[i] : 0;
        int x = v;
        #pragma unroll
        for (int o = 1; o < 32; o <<= 1) {
            int y = __shfl_up_sync(0xffffffffu, x, o);
            if ((t & 31) >= o) x += y;
        }
        if ((t & 31) == 31) wsum[t >> 5] = x;
        __syncthreads();
        if (t < 32) {
            int w = wsum[t];
            #pragma unroll
            for (int o = 1; o < 32; o <<= 1) {
                int y = __shfl_up_sync(0xffffffffu, w, o);
                if (t >= o) w += y;
            }
            wsum[t] = w;
        }
        __syncthreads();
        int incl = x + ((t >= 32) ? wsum[(t >> 5) - 1] : 0);
        int carry = carry_sh;
        if (i < N) g_offs[i] = carry + incl - v;   // exclusive
        __syncthreads();
        if (t == 1023) carry_sh = carry + incl;    // tile total
        __syncthreads();
    }
    if (t == 0) g_offs[N] = carry_sh;
}

__global__ void fill_kernel(const int* __restrict__ ei, int E) {
    int e = blockIdx.x * blockDim.x + threadIdx.x;
    if (e < E) {
        int d = ei[E + e];
        if (d >= 0 && d < MAX_N) {
            int pos = g_offs[d] + atomicAdd(&g_cur[d], 1);
            g_csr[pos] = ei[e];
        }
    }
}

// ---------------- GEMM1: h1 = x @ W1  (M x 256 @ 256 x 256) ------------------
// Double-buffered software pipeline (1 sync per k-tile) + fused attention-
// score epilogue (each 128-col block covers exactly 2 heads of 64 channels).
#define GP 132
__global__ __launch_bounds__(256) void gemm1_kernel(
    const float* __restrict__ A, const float* __restrict__ B,
    const float* __restrict__ att_s, const float* __restrict__ att_d, int M)
{
    __shared__ float As[2][16][GP];
    __shared__ float Bs[2][16][GP];
    int t  = threadIdx.x;
    int n0 = blockIdx.x * 128;
    int m0 = blockIdx.y * 128;
    int tx = t & 15, ty = t >> 4;

    // load-slot indices
    int a_r0 = t >> 2,          a_c0 = t & 3;
    int a_r1 = (t + 256) >> 2,  a_c1 = (t + 256) & 3;
    int b_r0 = t >> 5,          b_c0 = t & 31;
    int b_r1 = (t + 256) >> 5,  b_c1 = (t + 256) & 31;

    // attention vectors for this thread's 8 columns (one head)
    float asr[8], adr[8];
    #pragma unroll
    for (int j = 0; j < 8; j++) {
        asr[j] = __ldg(att_s + n0 + tx * 8 + j);
        adr[j] = __ldg(att_d + n0 + tx * 8 + j);
    }

    float acc[8][8];
    #pragma unroll
    for (int i = 0; i < 8; i++)
        #pragma unroll
        for (int j = 0; j < 8; j++) acc[i][j] = 0.f;

    float4 pa0, pa1, pb0, pb1;
    // prologue: load tile 0 into regs
    {
        int k0 = 0;
        pa0 = make_float4(0.f, 0.f, 0.f, 0.f);
        pa1 = pa0;
        if (m0 + a_r0 < M) pa0 = *reinterpret_cast<const float4*>(A + (size_t)(m0 + a_r0) * 256 + k0 + a_c0 * 4);
        if (m0 + a_r1 < M) pa1 = *reinterpret_cast<const float4*>(A + (size_t)(m0 + a_r1) * 256 + k0 + a_c1 * 4);
        pb0 = *reinterpret_cast<const float4*>(B + (size_t)(k0 + b_r0) * 256 + n0 + b_c0 * 4);
        pb1 = *reinterpret_cast<const float4*>(B + (size_t)(k0 + b_r1) * 256 + n0 + b_c1 * 4);
    }

    #pragma unroll
    for (int tile = 0; tile < 16; tile++) {
        int buf = tile & 1;
        // 1. store regs (tile) -> smem[buf]
        As[buf][a_c0 * 4 + 0][a_r0] = pa0.x; As[buf][a_c0 * 4 + 1][a_r0] = pa0.y;
        As[buf][a_c0 * 4 + 2][a_r0] = pa0.z; As[buf][a_c0 * 4 + 3][a_r0] = pa0.w;
        As[buf][a_c1 * 4 + 0][a_r1] = pa1.x; As[buf][a_c1 * 4 + 1][a_r1] = pa1.y;
        As[buf][a_c1 * 4 + 2][a_r1] = pa1.z; As[buf][a_c1 * 4 + 3][a_r1] = pa1.w;
        Bs[buf][b_r0][b_c0 * 4 + 0] = pb0.x; Bs[buf][b_r0][b_c0 * 4 + 1] = pb0.y;
        Bs[buf][b_r0][b_c0 * 4 + 2] = pb0.z; Bs[buf][b_r0][b_c0 * 4 + 3] = pb0.w;
        Bs[buf][b_r1][b_c1 * 4 + 0] = pb1.x; Bs[buf][b_r1][b_c1 * 4 + 1] = pb1.y;
        Bs[buf][b_r1][b_c1 * 4 + 2] = pb1.z; Bs[buf][b_r1][b_c1 * 4 + 3] = pb1.w;
        // 2. single sync
        __syncthreads();
        // 3. prefetch tile+1 into regs (latency hidden behind compute)
        if (tile < 15) {
            int k0 = (tile + 1) * 16;
            float4 z = make_float4(0.f, 0.f, 0.f, 0.f);
            pa0 = (m0 + a_r0 < M) ? *reinterpret_cast<const float4*>(A + (size_t)(m0 + a_r0) * 256 + k0 + a_c0 * 4) : z;
            pa1 = (m0 + a_r1 < M) ? *reinterpret_cast<const float4*>(A + (size_t)(m0 + a_r1) * 256 + k0 + a_c1 * 4) : z;
            pb0 = *reinterpret_cast<const float4*>(B + (size_t)(k0 + b_r0) * 256 + n0 + b_c0 * 4);
            pb1 = *reinterpret_cast<const float4*>(B + (size_t)(k0 + b_r1) * 256 + n0 + b_c1 * 4);
        }
        // 4. compute from smem[buf]
        #pragma unroll
        for (int k = 0; k < 16; k++) {
            float ra[8], rb[8];
            #pragma unroll
            for (int i = 0; i < 8; i++) ra[i] = As[buf][k][ty * 8 + i];
            #pragma unroll
            for (int i = 0; i < 8; i++) rb[i] = Bs[buf][k][tx * 8 + i];
            #pragma unroll
            for (int i = 0; i < 8; i++)
                #pragma unroll
                for (int j = 0; j < 8; j++) acc[i][j] += ra[i] * rb[j];
        }
    }

    // write h1
    #pragma unroll
    for (int i = 0; i < 8; i++) {
        int gr = m0 + ty * 8 + i;
        if (gr < M) {
            #pragma unroll
            for (int j = 0; j < 8; j++)
                g_h1[(size_t)gr * 256 + n0 + tx * 8 + j] = acc[i][j];
        }
    }

    // fused attention-score epilogue: per-row dot with att vectors.
    // This thread's 8 cols are inside head = (n0>>6) + (tx>>3); reduce over the
    // 8 lanes sharing that head (lane groups of 8: shfl_xor 1,2,4 stay inside).
    float ps[8], pd[8];
    #pragma unroll
    for (int i = 0; i < 8; i++) {
        float s = 0.f, d = 0.f;
        #pragma unroll
        for (int j = 0; j < 8; j++) { s += acc[i][j] * asr[j]; d += acc[i][j] * adr[j]; }
        ps[i] = s; pd[i] = d;
    }
    #pragma unroll
    for (int o = 1; o < 8; o <<= 1) {
        #pragma unroll
        for (int i = 0; i < 8; i++) {
            ps[i] += __shfl_xor_sync(0xffffffffu, ps[i], o);
            pd[i] += __shfl_xor_sync(0xffffffffu, pd[i], o);
        }
    }
    if ((tx & 7) == 0) {
        int head = (n0 >> 6) + (tx >> 3);
        #pragma unroll
        for (int i = 0; i < 8; i++) {
            int gr = m0 + ty * 8 + i;
            if (gr < M) {
                g_as1[gr * H1N + head] = ps[i];
                g_ad1[gr * H1N + head] = pd[i];
            }
        }
    }
}

// ---------------- fused per-dst softmax + aggregation, layer1 ----------------
__global__ __launch_bounds__(256) void node1_kernel(const float* __restrict__ b1)
{
    int n = blockIdx.x;
    int t = threadIdx.x;
    int off = g_offs[n];
    int deg = g_offs[n + 1] - off;
    int E = deg + 1;                 // +1 self loop

    __shared__ float sh_ad[H1N], sh_m[H1N], sh_inv[H1N];
    __shared__ float rm[8][H1N], rs[8][H1N];
    __shared__ int   ssrc[32];
    __shared__ float sw[H1N * 32];

    if (t < H1N) sh_ad[t] = g_ad1[n * H1N + t];
    __syncthreads();
    float adv[4] = { sh_ad[0], sh_ad[1], sh_ad[2], sh_ad[3] };

    // phase 1: online softmax (m, s) per head
    float m[4] = { NEGBIG, NEGBIG, NEGBIG, NEGBIG };
    float s[4] = { 0.f, 0.f, 0.f, 0.f };
    for (int i = t; i < E; i += 256) {
        int src = (i < deg) ? g_csr[off + i] : n;
        #pragma unroll
        for (int h = 0; h < 4; h++) {
            float lr = g_as1[src * 4 + h] + adv[h];
            lr = lr > 0.f ? lr : 0.2f * lr;
            if (lr > m[h]) { s[h] = s[h] * __expf(m[h] - lr) + 1.f; m[h] = lr; }
            else           { s[h] += __expf(lr - m[h]); }
        }
    }
    #pragma unroll
    for (int o = 16; o > 0; o >>= 1) {
        #pragma unroll
        for (int h = 0; h < 4; h++) {
            float m2 = __shfl_down_sync(0xffffffffu, m[h], o);
            float s2 = __shfl_down_sync(0xffffffffu, s[h], o);
            if (m2 > m[h]) { s[h] = s[h] * __expf(m[h] - m2) + s2; m[h] = m2; }
            else           { s[h] += s2 * __expf(m2 - m[h]); }
        }
    }
    if ((t & 31) == 0) {
        #pragma unroll
        for (int h = 0; h < 4; h++) { rm[t >> 5][h] = m[h]; rs[t >> 5][h] = s[h]; }
    }
    __syncthreads();
    if (t < H1N) {
        float M = NEGBIG, S = 0.f;
        #pragma unroll
        for (int w = 0; w < 8; w++) {
            float m2 = rm[w][t], s2 = rs[w][t];
            if (m2 > M) { S = S * __expf(M - m2) + s2; M = m2; }
            else        { S += s2 * __expf(m2 - M); }
        }
        sh_m[t] = M; sh_inv[t] = 1.f / (S + 1e-16f);
    }
    __syncthreads();

    // phase 2: alpha-weighted gather; thread t owns channel t
    int h = t >> 6;
    float acc = 0.f;
    for (int base = 0; base < E; base += 32) {
        int cnt = min(32, E - base);
        __syncthreads();
        if (t < cnt) {
            int i = base + t;
            int src = (i < deg) ? g_csr[off + i] : n;
            ssrc[t] = src;
            #pragma unroll
            for (int hh = 0; hh < 4; hh++) {
                float lr = g_as1[src * 4 + hh] + sh_ad[hh];
                lr = lr > 0.f ? lr : 0.2f * lr;
                sw[hh * 32 + t] = __expf(lr - sh_m[hh]) * sh_inv[hh];
            }
        }
        __syncthreads();
        const float* swh = &sw[h * 32];
        for (int j = 0; j < cnt; j++)
            acc += g_h1[(size_t)ssrc[j] * HC + t] * swh[j];
    }
    float v = acc + b1[t];
    g_h1o[(size_t)n * HC + t] = v > 0.f ? v : 0.f;
}

// ---------------- GEMM2 (+ attention-score epilogue), smem-staged ------------
__global__ __launch_bounds__(256) void gemm2_kernel(
    const float* __restrict__ W2, const float* __restrict__ att_s,
    const float* __restrict__ att_d, int N)
{
    __shared__ float Wt[16][260];   // W2 transposed: Wt[j][k]  (row stride 1040B, 16B-aligned)
    __shared__ float Xs[16][260];   // 16 node rows
    int t = threadIdx.x;
    for (int i = t; i < HC * F2; i += 256) {
        int k = i >> 4, j = i & 15;
        Wt[j][k] = W2[i];
    }
    int n0 = blockIdx.x * 16;
    for (int i = t; i < 16 * HC; i += 256) {
        int row = i >> 8, k = i & 255;
        int n = n0 + row;
        Xs[row][k] = (n < N) ? g_h1o[(size_t)n * HC + k] : 0.f;
    }
    __syncthreads();

    int r = t >> 4, j = t & 15;
    int n = n0 + r;
    float acc = 0.f;
    #pragma unroll
    for (int k = 0; k < HC; k += 4) {
        float4 xv = *reinterpret_cast<const float4*>(&Xs[r][k]);
        float4 wv = *reinterpret_cast<const float4*>(&Wt[j][k]);
        acc += xv.x * wv.x + xv.y * wv.y + xv.z * wv.z + xv.w * wv.w;
    }
    float ps = acc * att_s[j], pd = acc * att_d[j];
    #pragma unroll
    for (int o = 8; o > 0; o >>= 1) {
        ps += __shfl_xor_sync(0xffffffffu, ps, o);
        pd += __shfl_xor_sync(0xffffffffu, pd, o);
    }
    if (n < N) {
        g_h2[n * F2 + j] = acc;
        if (j == 0) { g_as2[n] = ps; g_ad2[n] = pd; }
    }
}

// ---------------- fused per-dst softmax + aggregation + log_softmax, layer2 --
__global__ __launch_bounds__(128) void node2_kernel(
    const float* __restrict__ b2, float* __restrict__ out)
{
    int n = blockIdx.x, t = threadIdx.x;
    int off = g_offs[n], deg = g_offs[n + 1] - off, E = deg + 1;

    __shared__ float sh_ad, sh_m, sh_inv;
    __shared__ float rm[4], rs[4];
    __shared__ int   ssrc[32];
    __shared__ float sw[32];
    __shared__ float sacc[128];
    __shared__ float sv[16];

    if (t == 0) sh_ad = g_ad2[n];
    __syncthreads();
    float ad = sh_ad;

    float m = NEGBIG, s = 0.f;
    for (int i = t; i < E; i += 128) {
        int src = (i < deg) ? g_csr[off + i] : n;
        float lr = g_as2[src] + ad;
        lr = lr > 0.f ? lr : 0.2f * lr;
        if (lr > m) { s = s * __expf(m - lr) + 1.f; m = lr; }
        else        { s += __expf(lr - m); }
    }
    #pragma unroll
    for (int o = 16; o > 0; o >>= 1) {
        float m2 = __shfl_down_sync(0xffffffffu, m, o);
        float s2 = __shfl_down_sync(0xffffffffu, s, o);
        if (m2 > m) { s = s * __expf(m - m2) + s2; m = m2; }
        else        { s += s2 * __expf(m2 - m); }
    }
    if ((t & 31) == 0) { rm[t >> 5] = m; rs[t >> 5] = s; }
    __syncthreads();
    if (t == 0) {
        float M = NEGBIG, S = 0.f;
        #pragma unroll
        for (int w = 0; w < 4; w++) {
            float m2 = rm[w], s2 = rs[w];
            if (m2 > M) { S = S * __expf(M - m2) + s2; M = m2; }
            else        { S += s2 * __expf(m2 - M); }
        }
        sh_m = M; sh_inv = 1.f / (S + 1e-16f);
    }
    __syncthreads();
    float fm = sh_m, fi = sh_inv;

    int g = t >> 4, c = t & 15;
    float acc = 0.f;
    for (int base = 0; base < E; base += 32) {
        int cnt = min(32, E - base);
        __syncthreads();
        if (t < cnt) {
            int i = base + t;
            int src = (i < deg) ? g_csr[off + i] : n;
            ssrc[t] = src;
            float lr = g_as2[src] + ad;
            lr = lr > 0.f ? lr : 0.2f * lr;
            sw[t] = __expf(lr - fm) * fi;
        }
        __syncthreads();
        for (int j = g; j < cnt; j += 8)
            acc += g_h2[ssrc[j] * F2 + c] * sw[j];
    }
    sacc[t] = acc;
    __syncthreads();
    if (t < 16) {
        float v = 0.f;
        #pragma unroll
        for (int w = 0; w < 8; w++) v += sacc[w * 16 + t];
        sv[t] = v + b2[t];
    }
    __syncthreads();
    if (t < 16) {
        float mx = NEGBIG;
        #pragma unroll
        for (int j = 0; j < 16; j++) mx = fmaxf(mx, sv[j]);
        float se = 0.f;
        #pragma unroll
        for (int j = 0; j < 16; j++) se += expf(sv[j] - mx);
        out[n * F2 + t] = sv[t] - mx - logf(se);
    }
}

// ---------------- launch -----------------------------------------------------
extern "C" void kernel_launch(void* const* d_in, const int* in_sizes, int n_in,
                              void* d_out, int out_size)
{
    const float* x   = (const float*)d_in[0];
    const int*   ei  = (const int*)d_in[1];   // int32! (JAX x64 disabled)
    const float* W1  = (const float*)d_in[2];
    const float* as1 = (const float*)d_in[3];
    const float* ad1 = (const float*)d_in[4];
    const float* b1  = (const float*)d_in[5];
    const float* W2  = (const float*)d_in[6];
    const float* as2 = (const float*)d_in[7];
    const float* ad2 = (const float*)d_in[8];
    const float* b2  = (const float*)d_in[9];
    float* out = (float*)d_out;

    int N = in_sizes[0] / FIN;   // 50000
    int E = in_sizes[1] / 2;     // 800000

    init_kernel<<<(N + 255) / 256, 256>>>(N);
    deg_kernel<<<(E + 255) / 256, 256>>>(ei, E);
    scan_kernel<<<1, 1024>>>(N);
    fill_kernel<<<(E + 255) / 256, 256>>>(ei, E);

    gemm1_kernel<<<dim3(2, (N + 127) / 128), 256>>>(x, W1, as1, ad1, N);
    node1_kernel<<<N, 256>>>(b1);

    gemm2_kernel<<<(N + 15) / 16, 256>>>(W2, as2, ad2, N);
    node2_kernel<<<N, 128>>>(b2, out);
}

// round 13
// speedup vs baseline: 1.8164x; 1.8164x over previous
#include <cuda_runtime.h>
#include <math.h>

// Problem constants (shapes fixed by the dataset)
#define MAX_N 50000
#define MAX_E 800000
#define FIN   256
#define HC    256     // H1*C1
#define H1N   4
#define C1N   64
#define F2    16

// ---------------- scratch (static device globals; no allocation) -------------
// float4-typed so gather kernels can issue aligned LDG.128
__device__ float4 g_h1v [MAX_N * (HC / 4)];   // x@W1
__device__ float4 g_h1ov[MAX_N * (HC / 4)];   // layer1 output (bias+relu)
#define g_h1  ((float*)g_h1v)
#define g_h1o ((float*)g_h1ov)
__device__ float  g_h2 [MAX_N * F2];          // h1o@W2
__device__ float4 g_as1v[MAX_N];              // [N][4] per-head src scores
__device__ float4 g_ad1v[MAX_N];
__device__ float  g_as2[MAX_N];
__device__ float  g_ad2[MAX_N];
__device__ int    g_deg [MAX_N];
__device__ int    g_cur [MAX_N];
__device__ int    g_offs[MAX_N + 1];
__device__ int    g_csr [MAX_E];              // src node ids grouped by dst

#define NEGBIG (-3.0e38f)
#define FULLM  0xffffffffu

// ---------------- CSR build --------------------------------------------------
__global__ void init_kernel(int N) {
    int i = blockIdx.x * blockDim.x + threadIdx.x;
    if (i < N) { g_deg[i] = 0; g_cur[i] = 0; }
}

// edge_index is INT32 (JAX x64 disabled: randint(dtype=int64) silently yields int32)
__global__ void deg_kernel(const int* __restrict__ ei, int E) {
    int e = blockIdx.x * blockDim.x + threadIdx.x;
    if (e < E) {
        int d = ei[E + e];
        if (d >= 0 && d < MAX_N) atomicAdd(&g_deg[d], 1);
    }
}

// single-block exclusive scan of g_deg -> g_offs (N up to 50000)
__global__ void scan_kernel(int N) {
    __shared__ int wsum[32];
    __shared__ int carry_sh;
    int t = threadIdx.x;
    if (t == 0) carry_sh = 0;
    __syncthreads();
    for (int base = 0; base < N; base += 1024) {
        int i = base + t;
        int v = (i < N) ? g_deg[i] : 0;
        int x = v;
        #pragma unroll
        for (int o = 1; o < 32; o <<= 1) {
            int y = __shfl_up_sync(FULLM, x, o);
            if ((t & 31) >= o) x += y;
        }
        if ((t & 31) == 31) wsum[t >> 5] = x;
        __syncthreads();
        if (t < 32) {
            int w = wsum[t];
            #pragma unroll
            for (int o = 1; o < 32; o <<= 1) {
                int y = __shfl_up_sync(FULLM, w, o);
                if (t >= o) w += y;
            }
            wsum[t] = w;
        }
        __syncthreads();
        int incl = x + ((t >= 32) ? wsum[(t >> 5) - 1] : 0);
        int carry = carry_sh;
        if (i < N) g_offs[i] = carry + incl - v;   // exclusive
        __syncthreads();
        if (t == 1023) carry_sh = carry + incl;    // tile total
        __syncthreads();
    }
    if (t == 0) g_offs[N] = carry_sh;
}

__global__ void fill_kernel(const int* __restrict__ ei, int E) {
    int e = blockIdx.x * blockDim.x + threadIdx.x;
    if (e < E) {
        int d = ei[E + e];
        if (d >= 0 && d < MAX_N) {
            int pos = g_offs[d] + atomicAdd(&g_cur[d], 1);
            g_csr[pos] = ei[e];
        }
    }
}

// ---------------- GEMM1: h1 = x @ W1  (M x 256 @ 256 x 256) ------------------
// (R9-proven version: 2 syncs per k-tile, single buffer)
#define GP 132
__global__ __launch_bounds__(256) void gemm1_kernel(
    const float* __restrict__ A, const float* __restrict__ B, int M)
{
    __shared__ float As[16][GP];
    __shared__ float Bs[16][GP];
    int t  = threadIdx.x;
    int n0 = blockIdx.x * 128;
    int m0 = blockIdx.y * 128;
    int tx = t & 15, ty = t >> 4;
    float acc[8][8];
    #pragma unroll
    for (int i = 0; i < 8; i++)
        #pragma unroll
        for (int j = 0; j < 8; j++) acc[i][j] = 0.f;

    for (int k0 = 0; k0 < 256; k0 += 16) {
        #pragma unroll
        for (int u = 0; u < 2; u++) {
            int idx = t + u * 256;
            int r = idx >> 2, c4 = idx & 3;
            float4 v = make_float4(0.f, 0.f, 0.f, 0.f);
            int gr = m0 + r;
            if (gr < M)
                v = *reinterpret_cast<const float4*>(A + (size_t)gr * 256 + k0 + c4 * 4);
            As[c4 * 4 + 0][r] = v.x; As[c4 * 4 + 1][r] = v.y;
            As[c4 * 4 + 2][r] = v.z; As[c4 * 4 + 3][r] = v.w;
        }
        #pragma unroll
        for (int u = 0; u < 2; u++) {
            int idx = t + u * 256;
            int r = idx >> 5, c4 = idx & 31;
            float4 v = *reinterpret_cast<const float4*>(B + (size_t)(k0 + r) * 256 + n0 + c4 * 4);
            Bs[r][c4 * 4 + 0] = v.x; Bs[r][c4 * 4 + 1] = v.y;
            Bs[r][c4 * 4 + 2] = v.z; Bs[r][c4 * 4 + 3] = v.w;
        }
        __syncthreads();
        #pragma unroll
        for (int k = 0; k < 16; k++) {
            float ra[8], rb[8];
            #pragma unroll
            for (int i = 0; i < 8; i++) ra[i] = As[k][ty * 8 + i];
            #pragma unroll
            for (int i = 0; i < 8; i++) rb[i] = Bs[k][tx * 8 + i];
            #pragma unroll
            for (int i = 0; i < 8; i++)
                #pragma unroll
                for (int j = 0; j < 8; j++) acc[i][j] += ra[i] * rb[j];
        }
        __syncthreads();
    }
    #pragma unroll
    for (int i = 0; i < 8; i++) {
        int gr = m0 + ty * 8 + i;
        if (gr < M) {
            #pragma unroll
            for (int j = 0; j < 8; j++)
                g_h1[(size_t)gr * 256 + n0 + tx * 8 + j] = acc[i][j];
        }
    }
}

// ---------------- attention scores layer1 (R9 version) -----------------------
__global__ __launch_bounds__(256) void attn1_kernel(
    const float* __restrict__ att_s, const float* __restrict__ att_d)
{
    int n = blockIdx.x, t = threadIdx.x;
    float v  = g_h1[(size_t)n * HC + t];
    float ps = v * att_s[t], pd = v * att_d[t];
    #pragma unroll
    for (int o = 16; o > 0; o >>= 1) {
        ps += __shfl_down_sync(FULLM, ps, o);
        pd += __shfl_down_sync(FULLM, pd, o);
    }
    __shared__ float S[8], D[8];
    if ((t & 31) == 0) { S[t >> 5] = ps; D[t >> 5] = pd; }
    __syncthreads();
    if (t < H1N) {
        reinterpret_cast<float*>(g_as1v)[n * H1N + t] = S[2 * t] + S[2 * t + 1];
        reinterpret_cast<float*>(g_ad1v)[n * H1N + t] = D[2 * t] + D[2 * t + 1];
    }
}

// ---------------- warp-per-node softmax + aggregation, layer1 ----------------
// One warp per dst node. Zero __syncthreads. Lane owns 8 contiguous channels
// (within one head). Per-32-edge staging: lane j computes edge j's 4 head
// weights; broadcast via shfl. ALL shfl_sync collectives are executed
// unconditionally by the full warp (loop bounds are warp-uniform).
__global__ __launch_bounds__(256) void node1_kernel(const float* __restrict__ b1, int N)
{
    int lane = threadIdx.x & 31;
    int n = blockIdx.x * 8 + (threadIdx.x >> 5);
    if (n >= N) return;   // whole warp exits together (n is warp-uniform)

    int off = g_offs[n];
    int deg = g_offs[n + 1] - off;
    int E = deg + 1;                 // +1 self loop

    float4 ad4 = g_ad1v[n];
    float adv[4] = { ad4.x, ad4.y, ad4.z, ad4.w };

    // phase 1: online softmax stats per head
    float m[4] = { NEGBIG, NEGBIG, NEGBIG, NEGBIG };
    float s[4] = { 0.f, 0.f, 0.f, 0.f };
    for (int i = lane; i < E; i += 32) {
        int src = (i < deg) ? g_csr[off + i] : n;
        float4 a4 = g_as1v[src];
        float av[4] = { a4.x, a4.y, a4.z, a4.w };
        #pragma unroll
        for (int h = 0; h < 4; h++) {
            float lr = av[h] + adv[h];
            lr = lr > 0.f ? lr : 0.2f * lr;
            if (lr > m[h]) { s[h] = s[h] * __expf(m[h] - lr) + 1.f; m[h] = lr; }
            else           { s[h] += __expf(lr - m[h]); }
        }
    }
    // butterfly merge: all lanes converge to warp totals
    #pragma unroll
    for (int o = 1; o < 32; o <<= 1) {
        #pragma unroll
        for (int h = 0; h < 4; h++) {
            float mo = __shfl_xor_sync(FULLM, m[h], o);
            float so = __shfl_xor_sync(FULLM, s[h], o);
            float Mn = fmaxf(m[h], mo);
            s[h] = s[h] * __expf(m[h] - Mn) + so * __expf(mo - Mn);
            m[h] = Mn;
        }
    }
    float inv[4];
    #pragma unroll
    for (int h = 0; h < 4; h++) inv[h] = 1.f / (s[h] + 1e-16f);

    // phase 2: alpha-weighted gather. lane owns channels [lane*8, lane*8+8),
    // all within head = lane>>3.
    int head = lane >> 3;
    float4 acc0 = make_float4(0.f, 0.f, 0.f, 0.f);
    float4 acc1 = make_float4(0.f, 0.f, 0.f, 0.f);
    for (int base = 0; base < E; base += 32) {
        int cnt = min(32, E - base);          // warp-uniform
        int srcj = n;
        float w0 = 0.f, w1 = 0.f, w2 = 0.f, w3 = 0.f;
        int i = base + lane;
        if (lane < cnt) {
            srcj = (i < deg) ? g_csr[off + i] : n;
            float4 a4 = g_as1v[srcj];
            float lr;
            lr = a4.x + adv[0]; lr = lr > 0.f ? lr : 0.2f * lr; w0 = __expf(lr - m[0]) * inv[0];
            lr = a4.y + adv[1]; lr = lr > 0.f ? lr : 0.2f * lr; w1 = __expf(lr - m[1]) * inv[1];
            lr = a4.z + adv[2]; lr = lr > 0.f ? lr : 0.2f * lr; w2 = __expf(lr - m[2]) * inv[2];
            lr = a4.w + adv[3]; lr = lr > 0.f ? lr : 0.2f * lr; w3 = __expf(lr - m[3]) * inv[3];
        }
        for (int j = 0; j < cnt; j++) {       // j warp-uniform
            int   src = __shfl_sync(FULLM, srcj, j);
            float b0  = __shfl_sync(FULLM, w0, j);
            float b1w = __shfl_sync(FULLM, w1, j);
            float b2w = __shfl_sync(FULLM, w2, j);
            float b3w = __shfl_sync(FULLM, w3, j);
            float w = (head == 0) ? b0 : (head == 1) ? b1w : (head == 2) ? b2w : b3w;
            const float4* row = g_h1v + (size_t)src * 64;
            float4 v0 = row[lane * 2];
            float4 v1 = row[lane * 2 + 1];
            acc0.x += v0.x * w; acc0.y += v0.y * w; acc0.z += v0.z * w; acc0.w += v0.w * w;
            acc1.x += v1.x * w; acc1.y += v1.y * w; acc1.z += v1.z * w; acc1.w += v1.w * w;
        }
    }
    // bias + relu + store
    const float4* b1v = reinterpret_cast<const float4*>(b1);
    float4 bb0 = b1v[lane * 2], bb1 = b1v[lane * 2 + 1];
    acc0.x = fmaxf(acc0.x + bb0.x, 0.f); acc0.y = fmaxf(acc0.y + bb0.y, 0.f);
    acc0.z = fmaxf(acc0.z + bb0.z, 0.f); acc0.w = fmaxf(acc0.w + bb0.w, 0.f);
    acc1.x = fmaxf(acc1.x + bb1.x, 0.f); acc1.y = fmaxf(acc1.y + bb1.y, 0.f);
    acc1.z = fmaxf(acc1.z + bb1.z, 0.f); acc1.w = fmaxf(acc1.w + bb1.w, 0.f);
    g_h1ov[(size_t)n * 64 + lane * 2]     = acc0;
    g_h1ov[(size_t)n * 64 + lane * 2 + 1] = acc1;
}

// ---------------- GEMM2 (+ attention-score epilogue), smem-staged ------------
__global__ __launch_bounds__(256) void gemm2_kernel(
    const float* __restrict__ W2, const float* __restrict__ att_s,
    const float* __restrict__ att_d, int N)
{
    __shared__ float Wt[16][260];   // W2 transposed: Wt[j][k]
    __shared__ float Xs[16][260];   // 16 node rows
    int t = threadIdx.x;
    for (int i = t; i < HC * F2; i += 256) {
        int k = i >> 4, j = i & 15;
        Wt[j][k] = W2[i];
    }
    int n0 = blockIdx.x * 16;
    for (int i = t; i < 16 * HC; i += 256) {
        int row = i >> 8, k = i & 255;
        int n = n0 + row;
        Xs[row][k] = (n < N) ? g_h1o[(size_t)n * HC + k] : 0.f;
    }
    __syncthreads();

    int r = t >> 4, j = t & 15;
    int n = n0 + r;
    float acc = 0.f;
    #pragma unroll
    for (int k = 0; k < HC; k += 4) {
        float4 xv = *reinterpret_cast<const float4*>(&Xs[r][k]);
        float4 wv = *reinterpret_cast<const float4*>(&Wt[j][k]);
        acc += xv.x * wv.x + xv.y * wv.y + xv.z * wv.z + xv.w * wv.w;
    }
    float ps = acc * att_s[j], pd = acc * att_d[j];
    #pragma unroll
    for (int o = 8; o > 0; o >>= 1) {
        ps += __shfl_xor_sync(FULLM, ps, o);
        pd += __shfl_xor_sync(FULLM, pd, o);
    }
    if (n < N) {
        g_h2[n * F2 + j] = acc;
        if (j == 0) { g_as2[n] = ps; g_ad2[n] = pd; }
    }
}

// ---------------- warp-per-node layer2 + fused log_softmax -------------------
// Lane owns channel c = lane&15; two half-warps process even/odd edges.
// FIX vs R11: broadcast shuffles are hoisted OUT of the divergent branch —
// all 32 lanes execute them with a clamped warp-uniform-varying index; only
// the accumulate is predicated. (The R11 version deadlocked when cnt was odd.)
__global__ __launch_bounds__(256) void node2_kernel(
    const float* __restrict__ b2, float* __restrict__ out, int N)
{
    int lane = threadIdx.x & 31;
    int n = blockIdx.x * 8 + (threadIdx.x >> 5);
    if (n >= N) return;   // whole warp exits together

    int off = g_offs[n], deg = g_offs[n + 1] - off, E = deg + 1;
    float ad = g_ad2[n];

    // phase 1: softmax stats
    float m = NEGBIG, s = 0.f;
    for (int i = lane; i < E; i += 32) {
        int src = (i < deg) ? g_csr[off + i] : n;
        float lr = g_as2[src] + ad;
        lr = lr > 0.f ? lr : 0.2f * lr;
        if (lr > m) { s = s * __expf(m - lr) + 1.f; m = lr; }
        else        { s += __expf(lr - m); }
    }
    #pragma unroll
    for (int o = 1; o < 32; o <<= 1) {
        float mo = __shfl_xor_sync(FULLM, m, o);
        float so = __shfl_xor_sync(FULLM, s, o);
        float Mn = fmaxf(m, mo);
        s = s * __expf(m - Mn) + so * __expf(mo - Mn);
        m = Mn;
    }
    float fi = 1.f / (s + 1e-16f);

    // phase 2: gather. half-warp g handles edges j0+g; shfl executed by ALL lanes.
    int c = lane & 15, g = lane >> 4;
    float acc = 0.f;
    for (int base = 0; base < E; base += 32) {
        int cnt = min(32, E - base);          // warp-uniform
        int srcj = n; float wj = 0.f;
        int i = base + lane;
        if (lane < cnt) {
            srcj = (i < deg) ? g_csr[off + i] : n;
            float lr = g_as2[srcj] + ad;
            lr = lr > 0.f ? lr : 0.2f * lr;
            wj = __expf(lr - m) * fi;
        }
        for (int j0 = 0; j0 < cnt; j0 += 2) {  // j0 warp-uniform
            int jj = j0 + g;
            int jc = jj < cnt ? jj : cnt - 1;  // clamp; shfl runs on all lanes
            int   src = __shfl_sync(FULLM, srcj, jc);
            float w   = __shfl_sync(FULLM, wj, jc);
            if (jj < cnt)
                acc += g_h2[src * F2 + c] * w;
        }
    }
    acc += __shfl_xor_sync(FULLM, acc, 16);   // combine the two halves

    float v = acc + b2[c];
    // log_softmax over the 16 channels (within each 16-lane segment)
    float mx = v;
    #pragma unroll
    for (int o = 1; o < 16; o <<= 1)
        mx = fmaxf(mx, __shfl_xor_sync(FULLM, mx, o, 16));
    float se = __expf(v - mx);
    #pragma unroll
    for (int o = 1; o < 16; o <<= 1)
        se += __shfl_xor_sync(FULLM, se, o, 16);
    if (lane < 16)
        out[n * F2 + c] = v - mx - __logf(se);
}

// ---------------- launch -----------------------------------------------------
extern "C" void kernel_launch(void* const* d_in, const int* in_sizes, int n_in,
                              void* d_out, int out_size)
{
    const float* x   = (const float*)d_in[0];
    const int*   ei  = (const int*)d_in[1];   // int32! (JAX x64 disabled)
    const float* W1  = (const float*)d_in[2];
    const float* as1 = (const float*)d_in[3];
    const float* ad1 = (const float*)d_in[4];
    const float* b1  = (const float*)d_in[5];
    const float* W2  = (const float*)d_in[6];
    const float* as2 = (const float*)d_in[7];
    const float* ad2 = (const float*)d_in[8];
    const float* b2  = (const float*)d_in[9];
    float* out = (float*)d_out;

    int N = in_sizes[0] / FIN;   // 50000
    int E = in_sizes[1] / 2;     // 800000

    init_kernel<<<(N + 255) / 256, 256>>>(N);
    deg_kernel<<<(E + 255) / 256, 256>>>(ei, E);
    scan_kernel<<<1, 1024>>>(N);
    fill_kernel<<<(E + 255) / 256, 256>>>(ei, E);

    gemm1_kernel<<<dim3(2, (N + 127) / 128), 256>>>(x, W1, N);
    attn1_kernel<<<N, 256>>>(as1, ad1);
    node1_kernel<<<(N + 7) / 8, 256>>>(b1, N);

    gemm2_kernel<<<(N + 15) / 16, 256>>>(W2, as2, ad2, N);
    node2_kernel<<<(N + 7) / 8, 256>>>(b2, out, N);
}

// round 16
// speedup vs baseline: 2.3749x; 1.3075x over previous
#include <cuda_runtime.h>
#include <stdint.h>
#include <math.h>

// Problem constants (shapes fixed by the dataset)
#define MAX_N 50000
#define MAX_E 800000
#define FIN   256
#define HC    256     // H1*C1
#define H1N   4
#define C1N   64
#define F2    16

// ---------------- scratch (static device globals; no allocation) -------------
// float4-typed so gather kernels can issue aligned LDG.128
__device__ float4 g_h1v [MAX_N * (HC / 4)];   // x@W1
__device__ float4 g_h1ov[MAX_N * (HC / 4)];   // layer1 output (bias+relu)
#define g_h1  ((float*)g_h1v)
#define g_h1o ((float*)g_h1ov)
__device__ float  g_h2 [MAX_N * F2];          // h1o@W2
__device__ float4 g_as1v[MAX_N];              // [N][4] per-head src scores
__device__ float4 g_ad1v[MAX_N];
__device__ float  g_as2[MAX_N];
__device__ float  g_ad2[MAX_N];
__device__ int    g_deg [MAX_N];
__device__ int    g_cur [MAX_N];
__device__ int    g_offs[MAX_N + 1];
__device__ int    g_csr [MAX_E];              // src node ids grouped by dst

#define NEGBIG (-3.0e38f)
#define FULLM  0xffffffffu

// ---------------- CSR build --------------------------------------------------
__global__ void init_kernel(int N) {
    int i = blockIdx.x * blockDim.x + threadIdx.x;
    if (i < N) { g_deg[i] = 0; g_cur[i] = 0; }
}

// edge_index is INT32 (JAX x64 disabled: randint(dtype=int64) silently yields int32)
__global__ void deg_kernel(const int* __restrict__ ei, int E) {
    int e = blockIdx.x * blockDim.x + threadIdx.x;
    if (e < E) {
        int d = ei[E + e];
        if (d >= 0 && d < MAX_N) atomicAdd(&g_deg[d], 1);
    }
}

// single-block exclusive scan of g_deg -> g_offs (N up to 50000)
__global__ void scan_kernel(int N) {
    __shared__ int wsum[32];
    __shared__ int carry_sh;
    int t = threadIdx.x;
    if (t == 0) carry_sh = 0;
    __syncthreads();
    for (int base = 0; base < N; base += 1024) {
        int i = base + t;
        int v = (i < N) ? g_deg[i] : 0;
        int x = v;
        #pragma unroll
        for (int o = 1; o < 32; o <<= 1) {
            int y = __shfl_up_sync(FULLM, x, o);
            if ((t & 31) >= o) x += y;
        }
        if ((t & 31) == 31) wsum[t >> 5] = x;
        __syncthreads();
        if (t < 32) {
            int w = wsum[t];
            #pragma unroll
            for (int o = 1; o < 32; o <<= 1) {
                int y = __shfl_up_sync(FULLM, w, o);
                if (t >= o) w += y;
            }
            wsum[t] = w;
        }
        __syncthreads();
        int incl = x + ((t >= 32) ? wsum[(t >> 5) - 1] : 0);
        int carry = carry_sh;
        if (i < N) g_offs[i] = carry + incl - v;   // exclusive
        __syncthreads();
        if (t == 1023) carry_sh = carry + incl;    // tile total
        __syncthreads();
    }
    if (t == 0) g_offs[N] = carry_sh;
}

__global__ void fill_kernel(const int* __restrict__ ei, int E) {
    int e = blockIdx.x * blockDim.x + threadIdx.x;
    if (e < E) {
        int d = ei[E + e];
        if (d >= 0 && d < MAX_N) {
            int pos = g_offs[d] + atomicAdd(&g_cur[d], 1);
            g_csr[pos] = ei[e];
        }
    }
}

// ---------------- GEMM1 (TF32 tensor cores): h1 = x @ W1 ---------------------
// 128x128 block tile, 8 warps (4 along M x 2 along N), warp tile 32x64,
// mma.sync.m16n8k8 tf32. Inputs rounded to tf32 (rna) at smem staging.
// Smem pads chosen for conflict-free fragment LDS:
//   As[128][36]: bank(4r+tig) distinct;  Bs[32][136]: bank(8*tig+gid) distinct.
__device__ __forceinline__ uint32_t f2tf32(float x) {
    uint32_t r;
    asm("cvt.rna.tf32.f32 %0, %1;" : "=r"(r) : "f"(x));
    return r;
}

__device__ __forceinline__ void mma_tf32(float* c, const uint32_t* a, const uint32_t* b) {
    asm volatile(
        "mma.sync.aligned.m16n8k8.row.col.f32.tf32.tf32.f32 "
        "{%0,%1,%2,%3}, {%4,%5,%6,%7}, {%8,%9}, {%0,%1,%2,%3};"
        : "+f"(c[0]), "+f"(c[1]), "+f"(c[2]), "+f"(c[3])
        : "r"(a[0]), "r"(a[1]), "r"(a[2]), "r"(a[3]), "r"(b[0]), "r"(b[1]));
}

__global__ __launch_bounds__(256) void gemm1_tf32_kernel(
    const float* __restrict__ A, const float* __restrict__ B, int M)
{
    __shared__ float As[128][36];    // 18.0 KB
    __shared__ float Bs[32][136];    // 17.4 KB
    int t = threadIdx.x;
    int lane = t & 31, warp = t >> 5;
    int wm = warp & 3, wn = warp >> 2;      // 4 m-warps x 2 n-warps
    int m0 = blockIdx.y * 128, n0 = blockIdx.x * 128;
    int gid = lane >> 2, tig = lane & 3;    // groupID, threadID-in-group

    float c[2][8][4];
    #pragma unroll
    for (int mt = 0; mt < 2; mt++)
        #pragma unroll
        for (int nt = 0; nt < 8; nt++)
            #pragma unroll
            for (int q = 0; q < 4; q++) c[mt][nt][q] = 0.f;

    for (int k0 = 0; k0 < 256; k0 += 32) {
        // stage A tile (128x32), tf32-rounded
        #pragma unroll
        for (int u = 0; u < 4; u++) {
            int linear = t + u * 256;
            int row = linear >> 3, cc = (linear & 7) * 4;
            float4 v = make_float4(0.f, 0.f, 0.f, 0.f);
            if (m0 + row < M)
                v = *reinterpret_cast<const float4*>(A + (size_t)(m0 + row) * 256 + k0 + cc);
            As[row][cc + 0] = __uint_as_float(f2tf32(v.x));
            As[row][cc + 1] = __uint_as_float(f2tf32(v.y));
            As[row][cc + 2] = __uint_as_float(f2tf32(v.z));
            As[row][cc + 3] = __uint_as_float(f2tf32(v.w));
        }
        // stage B tile (32x128), tf32-rounded
        #pragma unroll
        for (int u = 0; u < 4; u++) {
            int linear = t + u * 256;
            int row = linear >> 5, cc = (linear & 31) * 4;
            float4 v = *reinterpret_cast<const float4*>(B + (size_t)(k0 + row) * 256 + n0 + cc);
            Bs[row][cc + 0] = __uint_as_float(f2tf32(v.x));
            Bs[row][cc + 1] = __uint_as_float(f2tf32(v.y));
            Bs[row][cc + 2] = __uint_as_float(f2tf32(v.z));
            Bs[row][cc + 3] = __uint_as_float(f2tf32(v.w));
        }
        __syncthreads();

        #pragma unroll
        for (int ks = 0; ks < 4; ks++) {
            int kk = ks * 8;
            uint32_t a[2][4], b[8][2];
            #pragma unroll
            for (int mt = 0; mt < 2; mt++) {
                int r = wm * 32 + mt * 16 + gid;
                a[mt][0] = __float_as_uint(As[r    ][kk + tig]);
                a[mt][1] = __float_as_uint(As[r + 8][kk + tig]);
                a[mt][2] = __float_as_uint(As[r    ][kk + tig + 4]);
                a[mt][3] = __float_as_uint(As[r + 8][kk + tig + 4]);
            }
            #pragma unroll
            for (int nt = 0; nt < 8; nt++) {
                int col = wn * 64 + nt * 8 + gid;
                b[nt][0] = __float_as_uint(Bs[kk + tig    ][col]);
                b[nt][1] = __float_as_uint(Bs[kk + tig + 4][col]);
            }
            #pragma unroll
            for (int mt = 0; mt < 2; mt++)
                #pragma unroll
                for (int nt = 0; nt < 8; nt++)
                    mma_tf32(c[mt][nt], a[mt], b[nt]);
        }
        __syncthreads();
    }

    // epilogue: c0,c1 -> (row, 2tig..2tig+1); c2,c3 -> (row+8, same cols)
    #pragma unroll
    for (int mt = 0; mt < 2; mt++) {
        int r0 = m0 + wm * 32 + mt * 16 + gid;
        #pragma unroll
        for (int nt = 0; nt < 8; nt++) {
            int cc = n0 + wn * 64 + nt * 8 + 2 * tig;
            if (r0 < M)
                *reinterpret_cast<float2*>(&g_h1[(size_t)r0 * 256 + cc]) =
                    make_float2(c[mt][nt][0], c[mt][nt][1]);
            if (r0 + 8 < M)
                *reinterpret_cast<float2*>(&g_h1[(size_t)(r0 + 8) * 256 + cc]) =
                    make_float2(c[mt][nt][2], c[mt][nt][3]);
        }
    }
}

// ---------------- attention scores layer1 (R9 version) -----------------------
__global__ __launch_bounds__(256) void attn1_kernel(
    const float* __restrict__ att_s, const float* __restrict__ att_d)
{
    int n = blockIdx.x, t = threadIdx.x;
    float v  = g_h1[(size_t)n * HC + t];
    float ps = v * att_s[t], pd = v * att_d[t];
    #pragma unroll
    for (int o = 16; o > 0; o >>= 1) {
        ps += __shfl_down_sync(FULLM, ps, o);
        pd += __shfl_down_sync(FULLM, pd, o);
    }
    __shared__ float S[8], D[8];
    if ((t & 31) == 0) { S[t >> 5] = ps; D[t >> 5] = pd; }
    __syncthreads();
    if (t < H1N) {
        reinterpret_cast<float*>(g_as1v)[n * H1N + t] = S[2 * t] + S[2 * t + 1];
        reinterpret_cast<float*>(g_ad1v)[n * H1N + t] = D[2 * t] + D[2 * t + 1];
    }
}

// ---------------- warp-per-node softmax + aggregation, layer1 ----------------
__global__ __launch_bounds__(256) void node1_kernel(const float* __restrict__ b1, int N)
{
    int lane = threadIdx.x & 31;
    int n = blockIdx.x * 8 + (threadIdx.x >> 5);
    if (n >= N) return;   // whole warp exits together (n is warp-uniform)

    int off = g_offs[n];
    int deg = g_offs[n + 1] - off;
    int E = deg + 1;                 // +1 self loop

    float4 ad4 = g_ad1v[n];
    float adv[4] = { ad4.x, ad4.y, ad4.z, ad4.w };

    // phase 1: online softmax stats per head
    float m[4] = { NEGBIG, NEGBIG, NEGBIG, NEGBIG };
    float s[4] = { 0.f, 0.f, 0.f, 0.f };
    for (int i = lane; i < E; i += 32) {
        int src = (i < deg) ? g_csr[off + i] : n;
        float4 a4 = g_as1v[src];
        float av[4] = { a4.x, a4.y, a4.z, a4.w };
        #pragma unroll
        for (int h = 0; h < 4; h++) {
            float lr = av[h] + adv[h];
            lr = lr > 0.f ? lr : 0.2f * lr;
            if (lr > m[h]) { s[h] = s[h] * __expf(m[h] - lr) + 1.f; m[h] = lr; }
            else           { s[h] += __expf(lr - m[h]); }
        }
    }
    // butterfly merge: all lanes converge to warp totals
    #pragma unroll
    for (int o = 1; o < 32; o <<= 1) {
        #pragma unroll
        for (int h = 0; h < 4; h++) {
            float mo = __shfl_xor_sync(FULLM, m[h], o);
            float so = __shfl_xor_sync(FULLM, s[h], o);
            float Mn = fmaxf(m[h], mo);
            s[h] = s[h] * __expf(m[h] - Mn) + so * __expf(mo - Mn);
            m[h] = Mn;
        }
    }
    float inv[4];
    #pragma unroll
    for (int h = 0; h < 4; h++) inv[h] = 1.f / (s[h] + 1e-16f);

    // phase 2: alpha-weighted gather. lane owns channels [lane*8, lane*8+8).
    int head = lane >> 3;
    float4 acc0 = make_float4(0.f, 0.f, 0.f, 0.f);
    float4 acc1 = make_float4(0.f, 0.f, 0.f, 0.f);
    for (int base = 0; base < E; base += 32) {
        int cnt = min(32, E - base);          // warp-uniform
        int srcj = n;
        float w0 = 0.f, w1 = 0.f, w2 = 0.f, w3 = 0.f;
        int i = base + lane;
        if (lane < cnt) {
            srcj = (i < deg) ? g_csr[off + i] : n;
            float4 a4 = g_as1v[srcj];
            float lr;
            lr = a4.x + adv[0]; lr = lr > 0.f ? lr : 0.2f * lr; w0 = __expf(lr - m[0]) * inv[0];
            lr = a4.y + adv[1]; lr = lr > 0.f ? lr : 0.2f * lr; w1 = __expf(lr - m[1]) * inv[1];
            lr = a4.z + adv[2]; lr = lr > 0.f ? lr : 0.2f * lr; w2 = __expf(lr - m[2]) * inv[2];
            lr = a4.w + adv[3]; lr = lr > 0.f ? lr : 0.2f * lr; w3 = __expf(lr - m[3]) * inv[3];
        }
        for (int j = 0; j < cnt; j++) {       // j warp-uniform
            int   src = __shfl_sync(FULLM, srcj, j);
            float b0  = __shfl_sync(FULLM, w0, j);
            float b1w = __shfl_sync(FULLM, w1, j);
            float b2w = __shfl_sync(FULLM, w2, j);
            float b3w = __shfl_sync(FULLM, w3, j);
            float w = (head == 0) ? b0 : (head == 1) ? b1w : (head == 2) ? b2w : b3w;
            const float4* row = g_h1v + (size_t)src * 64;
            float4 v0 = row[lane * 2];
            float4 v1 = row[lane * 2 + 1];
            acc0.x += v0.x * w; acc0.y += v0.y * w; acc0.z += v0.z * w; acc0.w += v0.w * w;
            acc1.x += v1.x * w; acc1.y += v1.y * w; acc1.z += v1.z * w; acc1.w += v1.w * w;
        }
    }
    // bias + relu + store
    const float4* b1v = reinterpret_cast<const float4*>(b1);
    float4 bb0 = b1v[lane * 2], bb1 = b1v[lane * 2 + 1];
    acc0.x = fmaxf(acc0.x + bb0.x, 0.f); acc0.y = fmaxf(acc0.y + bb0.y, 0.f);
    acc0.z = fmaxf(acc0.z + bb0.z, 0.f); acc0.w = fmaxf(acc0.w + bb0.w, 0.f);
    acc1.x = fmaxf(acc1.x + bb1.x, 0.f); acc1.y = fmaxf(acc1.y + bb1.y, 0.f);
    acc1.z = fmaxf(acc1.z + bb1.z, 0.f); acc1.w = fmaxf(acc1.w + bb1.w, 0.f);
    g_h1ov[(size_t)n * 64 + lane * 2]     = acc0;
    g_h1ov[(size_t)n * 64 + lane * 2 + 1] = acc1;
}

// ---------------- GEMM2 (+ attention-score epilogue), smem-staged ------------
__global__ __launch_bounds__(256) void gemm2_kernel(
    const float* __restrict__ W2, const float* __restrict__ att_s,
    const float* __restrict__ att_d, int N)
{
    __shared__ float Wt[16][260];   // W2 transposed: Wt[j][k]
    __shared__ float Xs[16][260];   // 16 node rows
    int t = threadIdx.x;
    for (int i = t; i < HC * F2; i += 256) {
        int k = i >> 4, j = i & 15;
        Wt[j][k] = W2[i];
    }
    int n0 = blockIdx.x * 16;
    for (int i = t; i < 16 * HC; i += 256) {
        int row = i >> 8, k = i & 255;
        int n = n0 + row;
        Xs[row][k] = (n < N) ? g_h1o[(size_t)n * HC + k] : 0.f;
    }
    __syncthreads();

    int r = t >> 4, j = t & 15;
    int n = n0 + r;
    float acc = 0.f;
    #pragma unroll
    for (int k = 0; k < HC; k += 4) {
        float4 xv = *reinterpret_cast<const float4*>(&Xs[r][k]);
        float4 wv = *reinterpret_cast<const float4*>(&Wt[j][k]);
        acc += xv.x * wv.x + xv.y * wv.y + xv.z * wv.z + xv.w * wv.w;
    }
    float ps = acc * att_s[j], pd = acc * att_d[j];
    #pragma unroll
    for (int o = 8; o > 0; o >>= 1) {
        ps += __shfl_xor_sync(FULLM, ps, o);
        pd += __shfl_xor_sync(FULLM, pd, o);
    }
    if (n < N) {
        g_h2[n * F2 + j] = acc;
        if (j == 0) { g_as2[n] = ps; g_ad2[n] = pd; }
    }
}

// ---------------- warp-per-node layer2 + fused log_softmax -------------------
__global__ __launch_bounds__(256) void node2_kernel(
    const float* __restrict__ b2, float* __restrict__ out, int N)
{
    int lane = threadIdx.x & 31;
    int n = blockIdx.x * 8 + (threadIdx.x >> 5);
    if (n >= N) return;   // whole warp exits together

    int off = g_offs[n], deg = g_offs[n + 1] - off, E = deg + 1;
    float ad = g_ad2[n];

    // phase 1: softmax stats
    float m = NEGBIG, s = 0.f;
    for (int i = lane; i < E; i += 32) {
        int src = (i < deg) ? g_csr[off + i] : n;
        float lr = g_as2[src] + ad;
        lr = lr > 0.f ? lr : 0.2f * lr;
        if (lr > m) { s = s * __expf(m - lr) + 1.f; m = lr; }
        else        { s += __expf(lr - m); }
    }
    #pragma unroll
    for (int o = 1; o < 32; o <<= 1) {
        float mo = __shfl_xor_sync(FULLM, m, o);
        float so = __shfl_xor_sync(FULLM, s, o);
        float Mn = fmaxf(m, mo);
        s = s * __expf(m - Mn) + so * __expf(mo - Mn);
        m = Mn;
    }
    float fi = 1.f / (s + 1e-16f);

    // phase 2: gather. half-warp g handles edges j0+g; shfl executed by ALL lanes.
    int c = lane & 15, g = lane >> 4;
    float acc = 0.f;
    for (int base = 0; base < E; base += 32) {
        int cnt = min(32, E - base);          // warp-uniform
        int srcj = n; float wj = 0.f;
        int i = base + lane;
        if (lane < cnt) {
            srcj = (i < deg) ? g_csr[off + i] : n;
            float lr = g_as2[srcj] + ad;
            lr = lr > 0.f ? lr : 0.2f * lr;
            wj = __expf(lr - m) * fi;
        }
        for (int j0 = 0; j0 < cnt; j0 += 2) {  // j0 warp-uniform
            int jj = j0 + g;
            int jc = jj < cnt ? jj : cnt - 1;  // clamp; shfl runs on all lanes
            int   src = __shfl_sync(FULLM, srcj, jc);
            float w   = __shfl_sync(FULLM, wj, jc);
            if (jj < cnt)
                acc += g_h2[src * F2 + c] * w;
        }
    }
    acc += __shfl_xor_sync(FULLM, acc, 16);   // combine the two halves

    float v = acc + b2[c];
    // log_softmax over the 16 channels (within each 16-lane segment)
    float mx = v;
    #pragma unroll
    for (int o = 1; o < 16; o <<= 1)
        mx = fmaxf(mx, __shfl_xor_sync(FULLM, mx, o, 16));
    float se = __expf(v - mx);
    #pragma unroll
    for (int o = 1; o < 16; o <<= 1)
        se += __shfl_xor_sync(FULLM, se, o, 16);
    if (lane < 16)
        out[n * F2 + c] = v - mx - __logf(se);
}

// ---------------- launch -----------------------------------------------------
extern "C" void kernel_launch(void* const* d_in, const int* in_sizes, int n_in,
                              void* d_out, int out_size)
{
    const float* x   = (const float*)d_in[0];
    const int*   ei  = (const int*)d_in[1];   // int32! (JAX x64 disabled)
    const float* W1  = (const float*)d_in[2];
    const float* as1 = (const float*)d_in[3];
    const float* ad1 = (const float*)d_in[4];
    const float* b1  = (const float*)d_in[5];
    const float* W2  = (const float*)d_in[6];
    const float* as2 = (const float*)d_in[7];
    const float* ad2 = (const float*)d_in[8];
    const float* b2  = (const float*)d_in[9];
    float* out = (float*)d_out;

    int N = in_sizes[0] / FIN;   // 50000
    int E = in_sizes[1] / 2;     // 800000

    init_kernel<<<(N + 255) / 256, 256>>>(N);
    deg_kernel<<<(E + 255) / 256, 256>>>(ei, E);
    scan_kernel<<<1, 1024>>>(N);
    fill_kernel<<<(E + 255) / 256, 256>>>(ei, E);

    gemm1_tf32_kernel<<<dim3(2, (N + 127) / 128), 256>>>(x, W1, N);
    attn1_kernel<<<N, 256>>>(as1, ad1);
    node1_kernel<<<(N + 7) / 8, 256>>>(b1, N);

    gemm2_kernel<<<(N + 15) / 16, 256>>>(W2, as2, ad2, N);
    node2_kernel<<<(N + 7) / 8, 256>>>(b2, out, N);
}